// round 14
// baseline (speedup 1.0000x reference)
#include <cuda_runtime.h>
#include <cuda_bf16.h>
#include <stdint.h>
#include <math.h>

// ---------------- problem constants ----------------
#define B_     2
#define S_     2048
#define DIN_   256
#define H_     512
#define NH_    8
#define DH_    64
#define M_     (B_ * S_)          // 4096
#define QKV_N  (3 * H_)           // 1536
#define BH_    (B_ * NH_)         // 16
#define NQKV   (3 * QKV_N)        // 4608
#define OCATN  (3 * H_)           // 1536

#define LOG2E  1.44269504088896f

typedef __nv_bfloat16 bf16;

// ---------------- scratch (device globals) ----------------
__device__ float g_h   [M_ * H_];
__device__ float g_res [M_ * H_];
__device__ float g_bc  [H_];

__device__ bf16 g_xh [M_ * DIN_],  g_xl [M_ * DIN_];
__device__ bf16 g_Winh[H_ * DIN_], g_Winl[H_ * DIN_];
__device__ bf16 g_ipwh[3 * QKV_N * H_];
__device__ bf16 g_opwh[H_ * OCATN];
__device__ bf16 g_Wouth[H_ * H_];
__device__ bf16 g_hh [M_ * H_];
__device__ bf16 g_qh [3 * BH_ * S_ * DH_];
__device__ bf16 g_kh [3 * BH_ * S_ * DH_];
__device__ bf16 g_vh [3 * BH_ * S_ * DH_];
__device__ bf16 g_oh [M_ * OCATN];
__device__ bf16 g_cmh[M_ * H_];

// ---------------- helpers ----------------
__device__ __forceinline__ uint32_t smem_u32(const void* p) {
    uint32_t a;
    asm("{ .reg .u64 t; cvta.to.shared.u64 t, %1; cvt.u32.u64 %0, t; }" : "=r"(a) : "l"(p));
    return a;
}
__device__ __forceinline__ uint32_t swz128(uint32_t o) { return o ^ ((o >> 3) & 0x70); }
__device__ __forceinline__ uint32_t swz64 (uint32_t o) { return o ^ ((o >> 3) & 0x30); }
__device__ __forceinline__ float ex2(float x) {
    float y;
    asm("ex2.approx.ftz.f32 %0, %1;" : "=f"(y) : "f"(x));
    return y;
}

#define CP16(dst, src) asm volatile("cp.async.cg.shared.global [%0], [%1], 16;" :: "r"(dst), "l"(src))
#define CP_COMMIT()    asm volatile("cp.async.commit_group;" ::: "memory")
#define CP_WAIT1()     asm volatile("cp.async.wait_group 1;" ::: "memory")

__device__ __forceinline__ void mma_bf16(float* d, const uint32_t* a, const uint32_t* b) {
    asm volatile("mma.sync.aligned.m16n8k16.row.col.f32.bf16.bf16.f32 "
        "{%0,%1,%2,%3}, {%4,%5,%6,%7}, {%8,%9}, {%0,%1,%2,%3};"
        : "+f"(d[0]), "+f"(d[1]), "+f"(d[2]), "+f"(d[3])
        : "r"(a[0]), "r"(a[1]), "r"(a[2]), "r"(a[3]), "r"(b[0]), "r"(b[1]));
}
__device__ __forceinline__ void ldm_x4(uint32_t* r, uint32_t addr) {
    asm volatile("ldmatrix.sync.aligned.m8n8.x4.shared.b16 {%0,%1,%2,%3}, [%4];"
        : "=r"(r[0]), "=r"(r[1]), "=r"(r[2]), "=r"(r[3]) : "r"(addr));
}
__device__ __forceinline__ void ldm_x2(uint32_t* r, uint32_t addr) {
    asm volatile("ldmatrix.sync.aligned.m8n8.x2.shared.b16 {%0,%1}, [%2];"
        : "=r"(r[0]), "=r"(r[1]) : "r"(addr));
}
__device__ __forceinline__ void ldm_x4_t(uint32_t* r, uint32_t addr) {
    asm volatile("ldmatrix.sync.aligned.m8n8.x4.trans.shared.b16 {%0,%1,%2,%3}, [%4];"
        : "=r"(r[0]), "=r"(r[1]), "=r"(r[2]), "=r"(r[3]) : "r"(addr));
}
__device__ __forceinline__ uint32_t pack2(float a, float b) {
    __nv_bfloat162 hp = __floats2bfloat162_rn(a, b);
    return *(uint32_t*)&hp;
}

// ---------------- fused prep kernel (R10) ----------------
#define P_N0 (M_ * DIN_)
#define P_N1 (P_N0 + H_ * DIN_)
#define P_N2 (P_N1 + 3 * QKV_N * H_)
#define P_N3 (P_N2 + H_ * H_)
#define P_N4 (P_N3 + H_ * OCATN)
#define P_N5 (P_N4 + H_)
#define P_GRID ((P_N5 + 255) / 256)

__global__ void prep_kernel(const float* __restrict__ x, const float* __restrict__ W_in,
                            const float* __restrict__ ipw, const float* __restrict__ Wout,
                            const float* __restrict__ opw, const float* __restrict__ opb,
                            const float* __restrict__ sw)
{
    const int i = blockIdx.x * 256 + threadIdx.x;
    if (i < P_N0) {
        float v = x[i];
        bf16 h = __float2bfloat16(v);
        g_xh[i] = h;
        g_xl[i] = __float2bfloat16(v - __bfloat162float(h));
    } else if (i < P_N1) {
        const int j = i - P_N0;
        float v = W_in[j];
        bf16 h = __float2bfloat16(v);
        g_Winh[j] = h;
        g_Winl[j] = __float2bfloat16(v - __bfloat162float(h));
    } else if (i < P_N2) {
        const int j = i - P_N1;
        g_ipwh[j] = __float2bfloat16(ipw[j]);
    } else if (i < P_N3) {
        const int j = i - P_N2;
        g_Wouth[j] = __float2bfloat16(Wout[j]);
    } else if (i < P_N5) {
        float a = sw[0], b = sw[1], c = sw[2];
        float m = fmaxf(a, fmaxf(b, c));
        float e0 = expf(a - m), e1 = expf(b - m), e2 = expf(c - m);
        float inv = 1.0f / (e0 + e1 + e2);
        float w[3] = {e0 * inv, e1 * inv, e2 * inv};
        if (i < P_N4) {
            const int j = i - P_N3;
            const int h = j & 511;
            const int sc = (j >> 9) % 3;
            const int o = j / OCATN;
            g_opwh[j] = __float2bfloat16(w[sc] * opw[sc * (H_ * H_) + o * H_ + h]);
        } else {
            const int o = i - P_N4;
            g_bc[o] = w[0] * opb[o] + w[1] * opb[H_ + o] + w[2] * opb[2 * H_ + o];
        }
    }
}

// ---------------- HMMA GEMM: 128 threads, 4 warps (2m x 2n), warp tile 64x64 ----------------
// K-chunk 32, 3-stage cp.async, ONE barrier/chunk.
// modes: 0 = C fp32 + Chi, aux=pos (m%2048); 1 = qkv direct per-head writes;
//        2 = Chi only (+bias);               3 = C fp32, aux = residual
template<int SPLIT>
__global__ __launch_bounds__(128)
void gemm_mma(const bf16* __restrict__ Ah, const bf16* __restrict__ Al,
              const bf16* __restrict__ Wh, const bf16* __restrict__ Wl,
              const float* __restrict__ bias, float* __restrict__ C,
              bf16* __restrict__ Chi,
              bf16* __restrict__ qh, bf16* __restrict__ kh, bf16* __restrict__ vh,
              int N, int K, int mode, const float* __restrict__ aux)
{
    constexpr int STAGE = SPLIT ? 32768 : 16384;
    constexpr int WOFF  = SPLIT ? 16384 : 8192;
    extern __shared__ char sm[];
    const uint32_t sb = smem_u32(sm);
    const int tid = threadIdx.x, warp = tid >> 5, lane = tid & 31;
    const int warp_m = warp >> 1, warp_n = warp & 1;
    const int m0 = blockIdx.y * 128, n0 = blockIdx.x * 128;

    float acc[4][8][4];
#pragma unroll
    for (int a = 0; a < 4; a++)
#pragma unroll
        for (int bq = 0; bq < 8; bq++)
#pragma unroll
            for (int c = 0; c < 4; c++) acc[a][bq][c] = 0.0f;

    const int NC = K >> 5;

    auto issue = [&](int c, int stg) {
        const int k0 = c << 5;
        const uint32_t st = sb + stg * STAGE;
#pragma unroll
        for (int e = tid; e < 512; e += 128) {
            const int row = e >> 2, c16 = e & 3;
            const uint32_t so = swz64((uint32_t)(row * 64 + c16 * 16));
            CP16(st + so,        Ah + (size_t)(m0 + row) * K + k0 + c16 * 8);
            CP16(st + WOFF + so, Wh + (size_t)(n0 + row) * K + k0 + c16 * 8);
            if (SPLIT) {
                CP16(st + 8192 + so,  Al + (size_t)(m0 + row) * K + k0 + c16 * 8);
                CP16(st + 24576 + so, Wl + (size_t)(n0 + row) * K + k0 + c16 * 8);
            }
        }
    };

    issue(0, 0); CP_COMMIT();
    issue(1, 1); CP_COMMIT();

    int buf = 0;
    for (int c = 0; c < NC; c++) {
        CP_WAIT1();
        __syncthreads();
        if (c + 2 < NC) issue(c + 2, (buf + 2) % 3);
        CP_COMMIT();

        const uint32_t st = sb + buf * STAGE;
#pragma unroll
        for (int ks = 0; ks < 2; ks++) {
            uint32_t ah4[4][4], al4[4][4];
#pragma unroll
            for (int mt = 0; mt < 4; mt++) {
                uint32_t aoff = swz64((uint32_t)((warp_m * 64 + mt * 16 + (lane & 15)) * 64
                                    + ks * 32 + (lane >> 4) * 16));
                ldm_x4(ah4[mt], st + aoff);
                if (SPLIT) ldm_x4(al4[mt], st + 8192 + aoff);
            }
#pragma unroll
            for (int nt = 0; nt < 8; nt++) {
                uint32_t boff = swz64((uint32_t)((warp_n * 64 + nt * 8 + (lane & 7)) * 64
                                    + ks * 32 + ((lane >> 3) & 1) * 16));
                uint32_t bh2[2], bl2[2];
                ldm_x2(bh2, st + WOFF + boff);
                if (SPLIT) ldm_x2(bl2, st + 24576 + boff);
#pragma unroll
                for (int mt = 0; mt < 4; mt++) {
                    mma_bf16(acc[mt][nt], ah4[mt], bh2);
                    if (SPLIT) {
                        mma_bf16(acc[mt][nt], ah4[mt], bl2);
                        mma_bf16(acc[mt][nt], al4[mt], bh2);
                    }
                }
            }
        }
        buf = (buf + 1) % 3;
    }

    // ---- epilogue ----
#pragma unroll
    for (int mt = 0; mt < 4; mt++) {
#pragma unroll
        for (int nt = 0; nt < 8; nt++) {
            const int mrow = m0 + warp_m * 64 + mt * 16 + (lane >> 2);
            const int n = n0 + warp_n * 64 + nt * 8 + (lane & 3) * 2;
            const float2 b2 = *(const float2*)&bias[n];
#pragma unroll
            for (int half = 0; half < 2; half++) {
                const int m = mrow + half * 8;
                float2 v;
                v.x = acc[mt][nt][half * 2 + 0] + b2.x;
                v.y = acc[mt][nt][half * 2 + 1] + b2.y;
                if (mode == 0) {
                    float2 p = *(const float2*)&aux[(size_t)(m & (S_ - 1)) * N + n];
                    v.x += p.x; v.y += p.y;
                } else if (mode == 3) {
                    float2 p = *(const float2*)&aux[(size_t)m * N + n];
                    v.x += p.x; v.y += p.y;
                }
                if (mode == 1) {
                    const int i = n / QKV_N;
                    const int e = n - i * QKV_N;
                    const int t = e >> 9;
                    const int hd = (e >> 6) & 7;
                    const int dim = e & 63;
                    const int bb = m >> 11, ss = m & (S_ - 1);
                    const size_t dst = ((((size_t)i * BH_) + bb * NH_ + hd) * S_ + ss) * 64 + dim;
                    const float sc = (t == 0) ? (0.125f * LOG2E) : 1.0f;
                    bf16* ph = (t == 0) ? qh : (t == 1) ? kh : vh;
                    *(uint32_t*)&ph[dst] = pack2(v.x * sc, v.y * sc);
                } else {
                    if (C)   *(float2*)&C[(size_t)m * N + n] = v;
                    if (Chi) *(uint32_t*)&Chi[(size_t)m * N + n] = pack2(v.x, v.y);
                }
            }
        }
    }
}

// ---------------- HMMA flash attention (R10 proven, verbatim) ----------------
#define A_STG 16384
#define A_Q   (3 * A_STG)          // 49152
#define ASM_TOTAL (A_Q + 16384)    // 65536

__global__ __launch_bounds__(128, 2)
void attn_mma(const bf16* __restrict__ qh_, const bf16* __restrict__ kh_,
              const bf16* __restrict__ vh_, bf16* __restrict__ ohi)
{
    extern __shared__ char sm[];
    const uint32_t sb = smem_u32(sm);
    const int tid = threadIdx.x, warp = tid >> 5, lane = tid & 31;
    const int bh = blockIdx.y, b = bh >> 3, hd = bh & 7;
    const int z = blockIdx.z;
    const int scale = (z == 0) ? 5 : (z == 1) ? 21 : 63;
    const int q0 = blockIdx.x * 128;
    const int qw = warp * 32;

    const size_t zoff = ((size_t)z * BH_ + bh) * S_ * 64;
    const bf16* qh = qh_ + zoff;
    const bf16* kh = kh_ + zoff;
    const bf16* vh = vh_ + zoff;

    auto issue_kv = [&](int t, int stg) {
        const int kt = t * 64;
        const uint32_t st = sb + stg * A_STG;
#pragma unroll
        for (int e = tid; e < 512; e += 128) {
            const int row = e >> 3, c8 = e & 7;
            const uint32_t so = swz128((uint32_t)(row * 128 + c8 * 16));
            const size_t g = (size_t)(kt + row) * 64 + c8 * 8;
            CP16(st + so,        kh + g);
            CP16(st + 8192 + so, vh + g);
        }
    };

    for (int e = tid; e < 1024; e += 128) {
        const int row = e >> 3, c8 = e & 7;
        const uint32_t so = swz128((uint32_t)(row * 128 + c8 * 16));
        CP16(sb + A_Q + so, qh + (size_t)(q0 + row) * 64 + c8 * 8);
    }
    issue_kv(0, 0); CP_COMMIT();
    issue_kv(1, 1); CP_COMMIT();
    CP_WAIT1();
    __syncthreads();

    uint32_t qf[2][4][4];
#pragma unroll
    for (int h = 0; h < 2; h++)
#pragma unroll
        for (int ks = 0; ks < 4; ks++) {
            const uint32_t aoff = swz128((uint32_t)((qw + h * 16 + (lane & 15)) * 128
                                + (ks * 16 + (lane >> 4) * 8) * 2));
            ldm_x4(qf[h][ks], sb + A_Q + aoff);
        }

    const int rA = q0 + qw + (lane >> 2);
    const int rB = rA + 16;

    float o[2][8][4];
#pragma unroll
    for (int h = 0; h < 2; h++)
#pragma unroll
        for (int nt = 0; nt < 8; nt++)
#pragma unroll
            for (int c = 0; c < 4; c++) o[h][nt][c] = 0.0f;
    float lA0 = 0.f, lA1 = 0.f, lB0 = 0.f, lB1 = 0.f;

    const int NT = S_ / 64;
    int buf = 0;
    for (int t = 0; t < NT; t++) {
        const int kt = t * 64;
        CP_WAIT1();
        __syncthreads();
        if (t + 2 < NT) issue_kv(t + 2, (buf + 2) % 3);
        CP_COMMIT();

        const uint32_t st = sb + buf * A_STG;
        const bool tile_mask = (kt <= q0 + 127) && (kt + 63 >= q0 - scale);

#pragma unroll
        for (int c16 = 0; c16 < 4; c16++) {
            float s[2][2][4];
#pragma unroll
            for (int h = 0; h < 2; h++)
#pragma unroll
                for (int nb = 0; nb < 2; nb++)
#pragma unroll
                    for (int c = 0; c < 4; c++) s[h][nb][c] = 0.0f;

#pragma unroll
            for (int ks = 0; ks < 4; ks++) {
                const uint32_t boff = swz128((uint32_t)(
                    (c16 * 16 + (lane >> 4) * 8 + (lane & 7)) * 128
                    + (ks * 16 + ((lane >> 3) & 1) * 8) * 2));
                uint32_t kf[4];
                ldm_x4(kf, st + boff);
                mma_bf16(s[0][0], qf[0][ks], kf);
                mma_bf16(s[0][1], qf[0][ks], kf + 2);
                mma_bf16(s[1][0], qf[1][ks], kf);
                mma_bf16(s[1][1], qf[1][ks], kf + 2);
            }

            const int kc0 = kt + c16 * 16;
            if (tile_mask && kc0 <= q0 + 127 && kc0 + 15 >= q0 - scale) {
#pragma unroll
                for (int nb = 0; nb < 2; nb++) {
                    const int kj = kc0 + nb * 8 + (lane & 3) * 2;
#pragma unroll
                    for (int dk = 0; dk < 2; dk++) {
                        const int k = kj + dk;
                        if (k <= rA      && k >= rA - scale)      s[0][nb][dk]     = -1e30f;
                        if (k <= rA + 8  && k >= rA + 8 - scale)  s[0][nb][2 + dk] = -1e30f;
                        if (k <= rB      && k >= rB - scale)      s[1][nb][dk]     = -1e30f;
                        if (k <= rB + 8  && k >= rB + 8 - scale)  s[1][nb][2 + dk] = -1e30f;
                    }
                }
            }

            uint32_t pf[2][4];
#pragma unroll
            for (int h = 0; h < 2; h++) {
#pragma unroll
                for (int nb = 0; nb < 2; nb++)
#pragma unroll
                    for (int c = 0; c < 4; c++) s[h][nb][c] = ex2(s[h][nb][c]);
                pf[h][0] = pack2(s[h][0][0], s[h][0][1]);
                pf[h][1] = pack2(s[h][0][2], s[h][0][3]);
                pf[h][2] = pack2(s[h][1][0], s[h][1][1]);
                pf[h][3] = pack2(s[h][1][2], s[h][1][3]);
            }
            lA0 += s[0][0][0] + s[0][0][1] + s[0][1][0] + s[0][1][1];
            lA1 += s[0][0][2] + s[0][0][3] + s[0][1][2] + s[0][1][3];
            lB0 += s[1][0][0] + s[1][0][1] + s[1][1][0] + s[1][1][1];
            lB1 += s[1][0][2] + s[1][0][3] + s[1][1][2] + s[1][1][3];

#pragma unroll
            for (int dv = 0; dv < 4; dv++) {
                const uint32_t voff = swz128((uint32_t)(
                    (c16 * 16 + (lane & 15)) * 128
                    + (dv * 16 + (lane >> 4) * 8) * 2));
                uint32_t vf[4];
                ldm_x4_t(vf, st + 8192 + voff);
                mma_bf16(o[0][2 * dv],     pf[0], vf);
                mma_bf16(o[0][2 * dv + 1], pf[0], vf + 2);
                mma_bf16(o[1][2 * dv],     pf[1], vf);
                mma_bf16(o[1][2 * dv + 1], pf[1], vf + 2);
            }
        }
        buf = (buf + 1) % 3;
    }

    lA0 += __shfl_xor_sync(0xffffffffu, lA0, 1);
    lA0 += __shfl_xor_sync(0xffffffffu, lA0, 2);
    lA1 += __shfl_xor_sync(0xffffffffu, lA1, 1);
    lA1 += __shfl_xor_sync(0xffffffffu, lA1, 2);
    lB0 += __shfl_xor_sync(0xffffffffu, lB0, 1);
    lB0 += __shfl_xor_sync(0xffffffffu, lB0, 2);
    lB1 += __shfl_xor_sync(0xffffffffu, lB1, 1);
    lB1 += __shfl_xor_sync(0xffffffffu, lB1, 2);
    const float iA0 = 1.0f / lA0, iA1 = 1.0f / lA1;
    const float iB0 = 1.0f / lB0, iB1 = 1.0f / lB1;

#pragma unroll
    for (int h = 0; h < 2; h++) {
        const int row0 = (h == 0) ? rA : rB;
        const float i0 = (h == 0) ? iA0 : iB0;
        const float i1 = (h == 0) ? iA1 : iB1;
#pragma unroll
        for (int nt = 0; nt < 8; nt++) {
            const int col = nt * 8 + (lane & 3) * 2;
            const size_t base0 = (size_t)(b * S_ + row0)     * OCATN + z * H_ + hd * 64 + col;
            const size_t base1 = (size_t)(b * S_ + row0 + 8) * OCATN + z * H_ + hd * 64 + col;
            *(uint32_t*)&ohi[base0] = pack2(o[h][nt][0] * i0, o[h][nt][1] * i0);
            *(uint32_t*)&ohi[base1] = pack2(o[h][nt][2] * i1, o[h][nt][3] * i1);
        }
    }
}

// ---------------- layernorm ----------------
__global__ __launch_bounds__(256)
void ln_kernel(const float* __restrict__ res, const float* __restrict__ gamma,
               const float* __restrict__ beta, float* __restrict__ out)
{
    __shared__ float red[256];
    const int row = blockIdx.x;
    const int tid = threadIdx.x;
    const float* r = res + (size_t)row * H_;

    const float x0 = r[tid], x1 = r[tid + 256];
    red[tid] = x0 + x1;
    __syncthreads();
    for (int s = 128; s > 0; s >>= 1) {
        if (tid < s) red[tid] += red[tid + s];
        __syncthreads();
    }
    const float mu = red[0] * (1.0f / H_);
    __syncthreads();

    const float d0 = x0 - mu, d1 = x1 - mu;
    red[tid] = d0 * d0 + d1 * d1;
    __syncthreads();
    for (int s = 128; s > 0; s >>= 1) {
        if (tid < s) red[tid] += red[tid + s];
        __syncthreads();
    }
    const float var = red[0] * (1.0f / H_);
    const float inv = rsqrtf(var + 1e-5f);

    float* dst = out + (size_t)row * H_;
    dst[tid]       = d0 * inv * gamma[tid]       + beta[tid];
    dst[tid + 256] = d1 * inv * gamma[tid + 256] + beta[tid + 256];
}

// ---------------- launch (R10 structure) ----------------
extern "C" void kernel_launch(void* const* d_in, const int* in_sizes, int n_in,
                              void* d_out, int out_size)
{
    const float* x          = (const float*)d_in[0];
    const float* pos        = (const float*)d_in[2];
    const float* W_in       = (const float*)d_in[3];
    const float* b_in       = (const float*)d_in[4];
    const float* in_proj_w  = (const float*)d_in[5];
    const float* in_proj_b  = (const float*)d_in[6];
    const float* out_proj_w = (const float*)d_in[7];
    const float* out_proj_b = (const float*)d_in[8];
    const float* sw         = (const float*)d_in[9];
    const float* W_out      = (const float*)d_in[10];
    const float* b_out      = (const float*)d_in[11];
    const float* ln_gamma   = (const float*)d_in[12];
    const float* ln_beta    = (const float*)d_in[13];
    float* out = (float*)d_out;

    float *h, *res, *bc;
    cudaGetSymbolAddress((void**)&h,   g_h);
    cudaGetSymbolAddress((void**)&res, g_res);
    cudaGetSymbolAddress((void**)&bc,  g_bc);
    bf16 *xh, *xl, *Winh, *Winl, *ipwh, *opwh, *Wouth;
    bf16 *hh, *qh, *kh, *vh, *oh, *cmh;
    cudaGetSymbolAddress((void**)&xh, g_xh);     cudaGetSymbolAddress((void**)&xl, g_xl);
    cudaGetSymbolAddress((void**)&Winh, g_Winh); cudaGetSymbolAddress((void**)&Winl, g_Winl);
    cudaGetSymbolAddress((void**)&ipwh, g_ipwh);
    cudaGetSymbolAddress((void**)&opwh, g_opwh);
    cudaGetSymbolAddress((void**)&Wouth, g_Wouth);
    cudaGetSymbolAddress((void**)&hh, g_hh);
    cudaGetSymbolAddress((void**)&qh, g_qh);
    cudaGetSymbolAddress((void**)&kh, g_kh);
    cudaGetSymbolAddress((void**)&vh, g_vh);
    cudaGetSymbolAddress((void**)&oh, g_oh);
    cudaGetSymbolAddress((void**)&cmh, g_cmh);

    cudaFuncSetAttribute(gemm_mma<1>, cudaFuncAttributeMaxDynamicSharedMemorySize, 98304);
    cudaFuncSetAttribute(gemm_mma<0>, cudaFuncAttributeMaxDynamicSharedMemorySize, 49152);
    cudaFuncSetAttribute(attn_mma,    cudaFuncAttributeMaxDynamicSharedMemorySize, ASM_TOTAL);

    // 0) all conversions + weight fusion in one kernel
    prep_kernel<<<P_GRID, 256>>>(x, W_in, in_proj_w, W_out, out_proj_w, out_proj_b, sw);

    // 1) h = x @ W_in^T + b_in + pos  (split-precision; fp32 h + bf16 hh)
    gemm_mma<1><<<dim3(H_ / 128, M_ / 128), 128, 98304>>>(
        xh, xl, Winh, Winl, b_in, h, hh, 0, 0, 0, H_, DIN_, 0, pos);

    // 2) qkv for all 3 scales in one GEMM (N=4608), direct per-head q/k/v
    gemm_mma<0><<<dim3(NQKV / 128, M_ / 128), 128, 49152>>>(
        hh, (const bf16*)0, ipwh, (const bf16*)0, in_proj_b, (float*)0, (bf16*)0,
        qh, kh, vh, NQKV, H_, 1, (const float*)0);

    // 3) attention, all scales (grid.z), 32 q/warp, 64-key tiles, 3-stage
    attn_mma<<<dim3(S_ / 128, BH_, 3), 128, ASM_TOTAL>>>(qh, kh, vh, oh);

    // 4) comb = ocat @ Wc^T + bc (bf16 out)
    gemm_mma<0><<<dim3(H_ / 128, M_ / 128), 128, 49152>>>(
        oh, (const bf16*)0, opwh, (const bf16*)0, bc, (float*)0, cmh,
        0, 0, 0, H_, OCATN, 2, (const float*)0);

    // 5) res = comb @ W_out^T + b_out + h ; then LN
    gemm_mma<0><<<dim3(H_ / 128, M_ / 128), 128, 49152>>>(
        cmh, (const bf16*)0, Wouth, (const bf16*)0, b_out, res, (bf16*)0,
        0, 0, 0, H_, H_, 3, h);
    ln_kernel<<<M_, 256>>>(res, ln_gamma, ln_beta, out);
}

// round 15
// speedup vs baseline: 1.2615x; 1.2615x over previous
#include <cuda_runtime.h>
#include <cuda_bf16.h>
#include <stdint.h>
#include <math.h>

// ---------------- problem constants ----------------
#define B_     2
#define S_     2048
#define DIN_   256
#define H_     512
#define NH_    8
#define DH_    64
#define M_     (B_ * S_)          // 4096
#define QKV_N  (3 * H_)           // 1536
#define BH_    (B_ * NH_)         // 16
#define NQKV   (3 * QKV_N)        // 4608
#define OCATN  (3 * H_)           // 1536

#define LOG2E  1.44269504088896f

typedef __nv_bfloat16 bf16;

// ---------------- scratch (device globals) ----------------
__device__ float g_h   [M_ * H_];
__device__ float g_res [M_ * H_];
__device__ float g_bc  [H_];

__device__ bf16 g_xh [M_ * DIN_],  g_xl [M_ * DIN_];
__device__ bf16 g_Winh[H_ * DIN_], g_Winl[H_ * DIN_];
__device__ bf16 g_ipwh[3 * QKV_N * H_];
__device__ bf16 g_opwh[H_ * OCATN];
__device__ bf16 g_Wouth[H_ * H_];
__device__ bf16 g_hh [M_ * H_];
__device__ bf16 g_qh [3 * BH_ * S_ * DH_];
__device__ bf16 g_kh [3 * BH_ * S_ * DH_];
__device__ bf16 g_vh [3 * BH_ * S_ * DH_];
__device__ bf16 g_oh [M_ * OCATN];
__device__ bf16 g_cmh[M_ * H_];

// ---------------- helpers ----------------
__device__ __forceinline__ uint32_t smem_u32(const void* p) {
    uint32_t a;
    asm("{ .reg .u64 t; cvta.to.shared.u64 t, %1; cvt.u32.u64 %0, t; }" : "=r"(a) : "l"(p));
    return a;
}
__device__ __forceinline__ uint32_t swz128(uint32_t o) { return o ^ ((o >> 3) & 0x70); }
__device__ __forceinline__ uint32_t swz64 (uint32_t o) { return o ^ ((o >> 3) & 0x30); }
__device__ __forceinline__ float ex2(float x) {
    float y;
    asm("ex2.approx.ftz.f32 %0, %1;" : "=f"(y) : "f"(x));
    return y;
}

#define CP16(dst, src) asm volatile("cp.async.cg.shared.global [%0], [%1], 16;" :: "r"(dst), "l"(src))
#define CP_COMMIT()    asm volatile("cp.async.commit_group;" ::: "memory")
#define CP_WAIT1()     asm volatile("cp.async.wait_group 1;" ::: "memory")

__device__ __forceinline__ void mma_bf16(float* d, const uint32_t* a, const uint32_t* b) {
    asm volatile("mma.sync.aligned.m16n8k16.row.col.f32.bf16.bf16.f32 "
        "{%0,%1,%2,%3}, {%4,%5,%6,%7}, {%8,%9}, {%0,%1,%2,%3};"
        : "+f"(d[0]), "+f"(d[1]), "+f"(d[2]), "+f"(d[3])
        : "r"(a[0]), "r"(a[1]), "r"(a[2]), "r"(a[3]), "r"(b[0]), "r"(b[1]));
}
__device__ __forceinline__ void ldm_x4(uint32_t* r, uint32_t addr) {
    asm volatile("ldmatrix.sync.aligned.m8n8.x4.shared.b16 {%0,%1,%2,%3}, [%4];"
        : "=r"(r[0]), "=r"(r[1]), "=r"(r[2]), "=r"(r[3]) : "r"(addr));
}
__device__ __forceinline__ void ldm_x2(uint32_t* r, uint32_t addr) {
    asm volatile("ldmatrix.sync.aligned.m8n8.x2.shared.b16 {%0,%1}, [%2];"
        : "=r"(r[0]), "=r"(r[1]) : "r"(addr));
}
__device__ __forceinline__ void ldm_x4_t(uint32_t* r, uint32_t addr) {
    asm volatile("ldmatrix.sync.aligned.m8n8.x4.trans.shared.b16 {%0,%1,%2,%3}, [%4];"
        : "=r"(r[0]), "=r"(r[1]), "=r"(r[2]), "=r"(r[3]) : "r"(addr));
}
__device__ __forceinline__ uint32_t pack2(float a, float b) {
    __nv_bfloat162 hp = __floats2bfloat162_rn(a, b);
    return *(uint32_t*)&hp;
}

// ---------------- fused prep kernel ----------------
#define P_N0 (M_ * DIN_)
#define P_N1 (P_N0 + H_ * DIN_)
#define P_N2 (P_N1 + 3 * QKV_N * H_)
#define P_N3 (P_N2 + H_ * H_)
#define P_N4 (P_N3 + H_ * OCATN)
#define P_N5 (P_N4 + H_)
#define P_GRID ((P_N5 + 255) / 256)

__global__ void prep_kernel(const float* __restrict__ x, const float* __restrict__ W_in,
                            const float* __restrict__ ipw, const float* __restrict__ Wout,
                            const float* __restrict__ opw, const float* __restrict__ opb,
                            const float* __restrict__ sw)
{
    const int i = blockIdx.x * 256 + threadIdx.x;
    if (i < P_N0) {
        float v = x[i];
        bf16 h = __float2bfloat16(v);
        g_xh[i] = h;
        g_xl[i] = __float2bfloat16(v - __bfloat162float(h));
    } else if (i < P_N1) {
        const int j = i - P_N0;
        float v = W_in[j];
        bf16 h = __float2bfloat16(v);
        g_Winh[j] = h;
        g_Winl[j] = __float2bfloat16(v - __bfloat162float(h));
    } else if (i < P_N2) {
        const int j = i - P_N1;
        g_ipwh[j] = __float2bfloat16(ipw[j]);
    } else if (i < P_N3) {
        const int j = i - P_N2;
        g_Wouth[j] = __float2bfloat16(Wout[j]);
    } else if (i < P_N5) {
        float a = sw[0], b = sw[1], c = sw[2];
        float m = fmaxf(a, fmaxf(b, c));
        float e0 = expf(a - m), e1 = expf(b - m), e2 = expf(c - m);
        float inv = 1.0f / (e0 + e1 + e2);
        float w[3] = {e0 * inv, e1 * inv, e2 * inv};
        if (i < P_N4) {
            const int j = i - P_N3;
            const int h = j & 511;
            const int sc = (j >> 9) % 3;
            const int o = j / OCATN;
            g_opwh[j] = __float2bfloat16(w[sc] * opw[sc * (H_ * H_) + o * H_ + h]);
        } else {
            const int o = i - P_N4;
            g_bc[o] = w[0] * opb[o] + w[1] * opb[H_ + o] + w[2] * opb[2 * H_ + o];
        }
    }
}

// ---------------- HMMA GEMM (R10 config + occupancy-2 bound) ----------------
// block 128x128, 8 warps (2m x 4n), warp tile 64x32, K-chunk 32, 3-stage, ONE barrier/chunk.
// modes: 0 = C fp32 + Chi, aux=pos (m%2048); 1 = qkv direct per-head writes;
//        2 = Chi only (+bias);               3 = C fp32, aux = residual
template<int SPLIT>
__global__ __launch_bounds__(256, 2)
void gemm_mma(const bf16* __restrict__ Ah, const bf16* __restrict__ Al,
              const bf16* __restrict__ Wh, const bf16* __restrict__ Wl,
              const float* __restrict__ bias, float* __restrict__ C,
              bf16* __restrict__ Chi,
              bf16* __restrict__ qh, bf16* __restrict__ kh, bf16* __restrict__ vh,
              int N, int K, int mode, const float* __restrict__ aux)
{
    constexpr int STAGE = SPLIT ? 32768 : 16384;
    constexpr int WOFF  = SPLIT ? 16384 : 8192;
    extern __shared__ char sm[];
    const uint32_t sb = smem_u32(sm);
    const int tid = threadIdx.x, warp = tid >> 5, lane = tid & 31;
    const int warp_m = warp >> 2, warp_n = warp & 3;
    const int m0 = blockIdx.y * 128, n0 = blockIdx.x * 128;

    float acc[4][4][4];
#pragma unroll
    for (int a = 0; a < 4; a++)
#pragma unroll
        for (int bq = 0; bq < 4; bq++)
#pragma unroll
            for (int c = 0; c < 4; c++) acc[a][bq][c] = 0.0f;

    const int NC = K >> 5;

    auto issue = [&](int c, int stg) {
        const int k0 = c << 5;
        const uint32_t st = sb + stg * STAGE;
#pragma unroll
        for (int e = tid; e < 512; e += 256) {
            const int row = e >> 2, c16 = e & 3;
            const uint32_t so = swz64((uint32_t)(row * 64 + c16 * 16));
            CP16(st + so,        Ah + (size_t)(m0 + row) * K + k0 + c16 * 8);
            CP16(st + WOFF + so, Wh + (size_t)(n0 + row) * K + k0 + c16 * 8);
            if (SPLIT) {
                CP16(st + 8192 + so,  Al + (size_t)(m0 + row) * K + k0 + c16 * 8);
                CP16(st + 24576 + so, Wl + (size_t)(n0 + row) * K + k0 + c16 * 8);
            }
        }
    };

    issue(0, 0); CP_COMMIT();
    issue(1, 1); CP_COMMIT();

    int buf = 0;
    for (int c = 0; c < NC; c++) {
        CP_WAIT1();
        __syncthreads();
        if (c + 2 < NC) issue(c + 2, (buf + 2) % 3);
        CP_COMMIT();

        const uint32_t st = sb + buf * STAGE;
#pragma unroll
        for (int ks = 0; ks < 2; ks++) {
            uint32_t ah4[4][4], al4[4][4];
#pragma unroll
            for (int mt = 0; mt < 4; mt++) {
                uint32_t aoff = swz64((uint32_t)((warp_m * 64 + mt * 16 + (lane & 15)) * 64
                                    + ks * 32 + (lane >> 4) * 16));
                ldm_x4(ah4[mt], st + aoff);
                if (SPLIT) ldm_x4(al4[mt], st + 8192 + aoff);
            }
#pragma unroll
            for (int nt = 0; nt < 4; nt++) {
                uint32_t boff = swz64((uint32_t)((warp_n * 32 + nt * 8 + (lane & 7)) * 64
                                    + ks * 32 + ((lane >> 3) & 1) * 16));
                uint32_t bh2[2], bl2[2];
                ldm_x2(bh2, st + WOFF + boff);
                if (SPLIT) ldm_x2(bl2, st + 24576 + boff);
#pragma unroll
                for (int mt = 0; mt < 4; mt++) {
                    mma_bf16(acc[mt][nt], ah4[mt], bh2);
                    if (SPLIT) {
                        mma_bf16(acc[mt][nt], ah4[mt], bl2);
                        mma_bf16(acc[mt][nt], al4[mt], bh2);
                    }
                }
            }
        }
        buf = (buf + 1) % 3;
    }

    // ---- epilogue ----
#pragma unroll
    for (int mt = 0; mt < 4; mt++) {
#pragma unroll
        for (int nt = 0; nt < 4; nt++) {
            const int mrow = m0 + warp_m * 64 + mt * 16 + (lane >> 2);
            const int n = n0 + warp_n * 32 + nt * 8 + (lane & 3) * 2;
            const float2 b2 = *(const float2*)&bias[n];
#pragma unroll
            for (int half = 0; half < 2; half++) {
                const int m = mrow + half * 8;
                float2 v;
                v.x = acc[mt][nt][half * 2 + 0] + b2.x;
                v.y = acc[mt][nt][half * 2 + 1] + b2.y;
                if (mode == 0) {
                    float2 p = *(const float2*)&aux[(size_t)(m & (S_ - 1)) * N + n];
                    v.x += p.x; v.y += p.y;
                } else if (mode == 3) {
                    float2 p = *(const float2*)&aux[(size_t)m * N + n];
                    v.x += p.x; v.y += p.y;
                }
                if (mode == 1) {
                    const int i = n / QKV_N;
                    const int e = n - i * QKV_N;
                    const int t = e >> 9;
                    const int hd = (e >> 6) & 7;
                    const int dim = e & 63;
                    const int bb = m >> 11, ss = m & (S_ - 1);
                    const size_t dst = ((((size_t)i * BH_) + bb * NH_ + hd) * S_ + ss) * 64 + dim;
                    const float sc = (t == 0) ? (0.125f * LOG2E) : 1.0f;
                    bf16* ph = (t == 0) ? qh : (t == 1) ? kh : vh;
                    *(uint32_t*)&ph[dst] = pack2(v.x * sc, v.y * sc);
                } else {
                    if (C)   *(float2*)&C[(size_t)m * N + n] = v;
                    if (Chi) *(uint32_t*)&Chi[(size_t)m * N + n] = pack2(v.x, v.y);
                }
            }
        }
    }
}

// ---------------- HMMA flash attention (R10 proven, verbatim) ----------------
#define A_STG 16384
#define A_Q   (3 * A_STG)          // 49152
#define ASM_TOTAL (A_Q + 16384)    // 65536

__global__ __launch_bounds__(128, 2)
void attn_mma(const bf16* __restrict__ qh_, const bf16* __restrict__ kh_,
              const bf16* __restrict__ vh_, bf16* __restrict__ ohi)
{
    extern __shared__ char sm[];
    const uint32_t sb = smem_u32(sm);
    const int tid = threadIdx.x, warp = tid >> 5, lane = tid & 31;
    const int bh = blockIdx.y, b = bh >> 3, hd = bh & 7;
    const int z = blockIdx.z;
    const int scale = (z == 0) ? 5 : (z == 1) ? 21 : 63;
    const int q0 = blockIdx.x * 128;
    const int qw = warp * 32;

    const size_t zoff = ((size_t)z * BH_ + bh) * S_ * 64;
    const bf16* qh = qh_ + zoff;
    const bf16* kh = kh_ + zoff;
    const bf16* vh = vh_ + zoff;

    auto issue_kv = [&](int t, int stg) {
        const int kt = t * 64;
        const uint32_t st = sb + stg * A_STG;
#pragma unroll
        for (int e = tid; e < 512; e += 128) {
            const int row = e >> 3, c8 = e & 7;
            const uint32_t so = swz128((uint32_t)(row * 128 + c8 * 16));
            const size_t g = (size_t)(kt + row) * 64 + c8 * 8;
            CP16(st + so,        kh + g);
            CP16(st + 8192 + so, vh + g);
        }
    };

    for (int e = tid; e < 1024; e += 128) {
        const int row = e >> 3, c8 = e & 7;
        const uint32_t so = swz128((uint32_t)(row * 128 + c8 * 16));
        CP16(sb + A_Q + so, qh + (size_t)(q0 + row) * 64 + c8 * 8);
    }
    issue_kv(0, 0); CP_COMMIT();
    issue_kv(1, 1); CP_COMMIT();
    CP_WAIT1();
    __syncthreads();

    uint32_t qf[2][4][4];
#pragma unroll
    for (int h = 0; h < 2; h++)
#pragma unroll
        for (int ks = 0; ks < 4; ks++) {
            const uint32_t aoff = swz128((uint32_t)((qw + h * 16 + (lane & 15)) * 128
                                + (ks * 16 + (lane >> 4) * 8) * 2));
            ldm_x4(qf[h][ks], sb + A_Q + aoff);
        }

    const int rA = q0 + qw + (lane >> 2);
    const int rB = rA + 16;

    float o[2][8][4];
#pragma unroll
    for (int h = 0; h < 2; h++)
#pragma unroll
        for (int nt = 0; nt < 8; nt++)
#pragma unroll
            for (int c = 0; c < 4; c++) o[h][nt][c] = 0.0f;
    float lA0 = 0.f, lA1 = 0.f, lB0 = 0.f, lB1 = 0.f;

    const int NT = S_ / 64;
    int buf = 0;
    for (int t = 0; t < NT; t++) {
        const int kt = t * 64;
        CP_WAIT1();
        __syncthreads();
        if (t + 2 < NT) issue_kv(t + 2, (buf + 2) % 3);
        CP_COMMIT();

        const uint32_t st = sb + buf * A_STG;
        const bool tile_mask = (kt <= q0 + 127) && (kt + 63 >= q0 - scale);

#pragma unroll
        for (int c16 = 0; c16 < 4; c16++) {
            float s[2][2][4];
#pragma unroll
            for (int h = 0; h < 2; h++)
#pragma unroll
                for (int nb = 0; nb < 2; nb++)
#pragma unroll
                    for (int c = 0; c < 4; c++) s[h][nb][c] = 0.0f;

#pragma unroll
            for (int ks = 0; ks < 4; ks++) {
                const uint32_t boff = swz128((uint32_t)(
                    (c16 * 16 + (lane >> 4) * 8 + (lane & 7)) * 128
                    + (ks * 16 + ((lane >> 3) & 1) * 8) * 2));
                uint32_t kf[4];
                ldm_x4(kf, st + boff);
                mma_bf16(s[0][0], qf[0][ks], kf);
                mma_bf16(s[0][1], qf[0][ks], kf + 2);
                mma_bf16(s[1][0], qf[1][ks], kf);
                mma_bf16(s[1][1], qf[1][ks], kf + 2);
            }

            const int kc0 = kt + c16 * 16;
            if (tile_mask && kc0 <= q0 + 127 && kc0 + 15 >= q0 - scale) {
#pragma unroll
                for (int nb = 0; nb < 2; nb++) {
                    const int kj = kc0 + nb * 8 + (lane & 3) * 2;
#pragma unroll
                    for (int dk = 0; dk < 2; dk++) {
                        const int k = kj + dk;
                        if (k <= rA      && k >= rA - scale)      s[0][nb][dk]     = -1e30f;
                        if (k <= rA + 8  && k >= rA + 8 - scale)  s[0][nb][2 + dk] = -1e30f;
                        if (k <= rB      && k >= rB - scale)      s[1][nb][dk]     = -1e30f;
                        if (k <= rB + 8  && k >= rB + 8 - scale)  s[1][nb][2 + dk] = -1e30f;
                    }
                }
            }

            uint32_t pf[2][4];
#pragma unroll
            for (int h = 0; h < 2; h++) {
#pragma unroll
                for (int nb = 0; nb < 2; nb++)
#pragma unroll
                    for (int c = 0; c < 4; c++) s[h][nb][c] = ex2(s[h][nb][c]);
                pf[h][0] = pack2(s[h][0][0], s[h][0][1]);
                pf[h][1] = pack2(s[h][0][2], s[h][0][3]);
                pf[h][2] = pack2(s[h][1][0], s[h][1][1]);
                pf[h][3] = pack2(s[h][1][2], s[h][1][3]);
            }
            lA0 += s[0][0][0] + s[0][0][1] + s[0][1][0] + s[0][1][1];
            lA1 += s[0][0][2] + s[0][0][3] + s[0][1][2] + s[0][1][3];
            lB0 += s[1][0][0] + s[1][0][1] + s[1][1][0] + s[1][1][1];
            lB1 += s[1][0][2] + s[1][0][3] + s[1][1][2] + s[1][1][3];

#pragma unroll
            for (int dv = 0; dv < 4; dv++) {
                const uint32_t voff = swz128((uint32_t)(
                    (c16 * 16 + (lane & 15)) * 128
                    + (dv * 16 + (lane >> 4) * 8) * 2));
                uint32_t vf[4];
                ldm_x4_t(vf, st + 8192 + voff);
                mma_bf16(o[0][2 * dv],     pf[0], vf);
                mma_bf16(o[0][2 * dv + 1], pf[0], vf + 2);
                mma_bf16(o[1][2 * dv],     pf[1], vf);
                mma_bf16(o[1][2 * dv + 1], pf[1], vf + 2);
            }
        }
        buf = (buf + 1) % 3;
    }

    lA0 += __shfl_xor_sync(0xffffffffu, lA0, 1);
    lA0 += __shfl_xor_sync(0xffffffffu, lA0, 2);
    lA1 += __shfl_xor_sync(0xffffffffu, lA1, 1);
    lA1 += __shfl_xor_sync(0xffffffffu, lA1, 2);
    lB0 += __shfl_xor_sync(0xffffffffu, lB0, 1);
    lB0 += __shfl_xor_sync(0xffffffffu, lB0, 2);
    lB1 += __shfl_xor_sync(0xffffffffu, lB1, 1);
    lB1 += __shfl_xor_sync(0xffffffffu, lB1, 2);
    const float iA0 = 1.0f / lA0, iA1 = 1.0f / lA1;
    const float iB0 = 1.0f / lB0, iB1 = 1.0f / lB1;

#pragma unroll
    for (int h = 0; h < 2; h++) {
        const int row0 = (h == 0) ? rA : rB;
        const float i0 = (h == 0) ? iA0 : iB0;
        const float i1 = (h == 0) ? iA1 : iB1;
#pragma unroll
        for (int nt = 0; nt < 8; nt++) {
            const int col = nt * 8 + (lane & 3) * 2;
            const size_t base0 = (size_t)(b * S_ + row0)     * OCATN + z * H_ + hd * 64 + col;
            const size_t base1 = (size_t)(b * S_ + row0 + 8) * OCATN + z * H_ + hd * 64 + col;
            *(uint32_t*)&ohi[base0] = pack2(o[h][nt][0] * i0, o[h][nt][1] * i0);
            *(uint32_t*)&ohi[base1] = pack2(o[h][nt][2] * i1, o[h][nt][3] * i1);
        }
    }
}

// ---------------- layernorm ----------------
__global__ __launch_bounds__(256)
void ln_kernel(const float* __restrict__ res, const float* __restrict__ gamma,
               const float* __restrict__ beta, float* __restrict__ out)
{
    __shared__ float red[256];
    const int row = blockIdx.x;
    const int tid = threadIdx.x;
    const float* r = res + (size_t)row * H_;

    const float x0 = r[tid], x1 = r[tid + 256];
    red[tid] = x0 + x1;
    __syncthreads();
    for (int s = 128; s > 0; s >>= 1) {
        if (tid < s) red[tid] += red[tid + s];
        __syncthreads();
    }
    const float mu = red[0] * (1.0f / H_);
    __syncthreads();

    const float d0 = x0 - mu, d1 = x1 - mu;
    red[tid] = d0 * d0 + d1 * d1;
    __syncthreads();
    for (int s = 128; s > 0; s >>= 1) {
        if (tid < s) red[tid] += red[tid + s];
        __syncthreads();
    }
    const float var = red[0] * (1.0f / H_);
    const float inv = rsqrtf(var + 1e-5f);

    float* dst = out + (size_t)row * H_;
    dst[tid]       = d0 * inv * gamma[tid]       + beta[tid];
    dst[tid + 256] = d1 * inv * gamma[tid + 256] + beta[tid + 256];
}

// ---------------- launch (R10 structure, verbatim) ----------------
extern "C" void kernel_launch(void* const* d_in, const int* in_sizes, int n_in,
                              void* d_out, int out_size)
{
    const float* x          = (const float*)d_in[0];
    const float* pos        = (const float*)d_in[2];
    const float* W_in       = (const float*)d_in[3];
    const float* b_in       = (const float*)d_in[4];
    const float* in_proj_w  = (const float*)d_in[5];
    const float* in_proj_b  = (const float*)d_in[6];
    const float* out_proj_w = (const float*)d_in[7];
    const float* out_proj_b = (const float*)d_in[8];
    const float* sw         = (const float*)d_in[9];
    const float* W_out      = (const float*)d_in[10];
    const float* b_out      = (const float*)d_in[11];
    const float* ln_gamma   = (const float*)d_in[12];
    const float* ln_beta    = (const float*)d_in[13];
    float* out = (float*)d_out;

    float *h, *res, *bc;
    cudaGetSymbolAddress((void**)&h,   g_h);
    cudaGetSymbolAddress((void**)&res, g_res);
    cudaGetSymbolAddress((void**)&bc,  g_bc);
    bf16 *xh, *xl, *Winh, *Winl, *ipwh, *opwh, *Wouth;
    bf16 *hh, *qh, *kh, *vh, *oh, *cmh;
    cudaGetSymbolAddress((void**)&xh, g_xh);     cudaGetSymbolAddress((void**)&xl, g_xl);
    cudaGetSymbolAddress((void**)&Winh, g_Winh); cudaGetSymbolAddress((void**)&Winl, g_Winl);
    cudaGetSymbolAddress((void**)&ipwh, g_ipwh);
    cudaGetSymbolAddress((void**)&opwh, g_opwh);
    cudaGetSymbolAddress((void**)&Wouth, g_Wouth);
    cudaGetSymbolAddress((void**)&hh, g_hh);
    cudaGetSymbolAddress((void**)&qh, g_qh);
    cudaGetSymbolAddress((void**)&kh, g_kh);
    cudaGetSymbolAddress((void**)&vh, g_vh);
    cudaGetSymbolAddress((void**)&oh, g_oh);
    cudaGetSymbolAddress((void**)&cmh, g_cmh);

    cudaFuncSetAttribute(gemm_mma<1>, cudaFuncAttributeMaxDynamicSharedMemorySize, 98304);
    cudaFuncSetAttribute(gemm_mma<0>, cudaFuncAttributeMaxDynamicSharedMemorySize, 49152);
    cudaFuncSetAttribute(attn_mma,    cudaFuncAttributeMaxDynamicSharedMemorySize, ASM_TOTAL);

    // 0) all conversions + weight fusion in one kernel
    prep_kernel<<<P_GRID, 256>>>(x, W_in, in_proj_w, W_out, out_proj_w, out_proj_b, sw);

    // 1) h = x @ W_in^T + b_in + pos  (split-precision; fp32 h + bf16 hh)
    gemm_mma<1><<<dim3(H_ / 128, M_ / 128), 256, 98304>>>(
        xh, xl, Winh, Winl, b_in, h, hh, 0, 0, 0, H_, DIN_, 0, pos);

    // 2) qkv for all 3 scales in one GEMM (N=4608), direct per-head q/k/v
    gemm_mma<0><<<dim3(NQKV / 128, M_ / 128), 256, 49152>>>(
        hh, (const bf16*)0, ipwh, (const bf16*)0, in_proj_b, (float*)0, (bf16*)0,
        qh, kh, vh, NQKV, H_, 1, (const float*)0);

    // 3) attention, all scales (grid.z), 32 q/warp, 64-key tiles, 3-stage
    attn_mma<<<dim3(S_ / 128, BH_, 3), 128, ASM_TOTAL>>>(qh, kh, vh, oh);

    // 4) comb = ocat @ Wc^T + bc (bf16 out)
    gemm_mma<0><<<dim3(H_ / 128, M_ / 128), 256, 49152>>>(
        oh, (const bf16*)0, opwh, (const bf16*)0, bc, (float*)0, cmh,
        0, 0, 0, H_, OCATN, 2, (const float*)0);

    // 5) res = comb @ W_out^T + b_out + h ; then LN
    gemm_mma<0><<<dim3(H_ / 128, M_ / 128), 256, 49152>>>(
        cmh, (const bf16*)0, Wouth, (const bf16*)0, b_out, res, (bf16*)0,
        0, 0, 0, H_, H_, 3, h);
    ln_kernel<<<M_, 256>>>(res, ln_gamma, ln_beta, out);
}

// round 16
// speedup vs baseline: 1.3103x; 1.0387x over previous
#include <cuda_runtime.h>
#include <cuda_bf16.h>
#include <stdint.h>
#include <math.h>

// ---------------- problem constants ----------------
#define B_     2
#define S_     2048
#define DIN_   256
#define H_     512
#define NH_    8
#define DH_    64
#define M_     (B_ * S_)          // 4096
#define QKV_N  (3 * H_)           // 1536
#define BH_    (B_ * NH_)         // 16
#define NQKV   (3 * QKV_N)        // 4608
#define OCATN  (3 * H_)           // 1536

#define LOG2E  1.44269504088896f

typedef __nv_bfloat16 bf16;

// ---------------- scratch (device globals) ----------------
__device__ float g_h   [M_ * H_];
__device__ float g_res [M_ * H_];
__device__ float g_bc  [H_];

__device__ bf16 g_xh [M_ * DIN_],  g_xl [M_ * DIN_];
__device__ bf16 g_Winh[H_ * DIN_], g_Winl[H_ * DIN_];
__device__ bf16 g_ipwh[3 * QKV_N * H_];
__device__ bf16 g_opwh[H_ * OCATN];
__device__ bf16 g_Wouth[H_ * H_];
__device__ bf16 g_hh [M_ * H_];
__device__ bf16 g_qh [3 * BH_ * S_ * DH_];
__device__ bf16 g_kh [3 * BH_ * S_ * DH_];
__device__ bf16 g_vh [3 * BH_ * S_ * DH_];
__device__ bf16 g_oh [M_ * OCATN];
__device__ bf16 g_cmh[M_ * H_];

// ---------------- helpers ----------------
__device__ __forceinline__ uint32_t smem_u32(const void* p) {
    uint32_t a;
    asm("{ .reg .u64 t; cvta.to.shared.u64 t, %1; cvt.u32.u64 %0, t; }" : "=r"(a) : "l"(p));
    return a;
}
__device__ __forceinline__ uint32_t swz128(uint32_t o) { return o ^ ((o >> 3) & 0x70); }
__device__ __forceinline__ uint32_t swz64 (uint32_t o) { return o ^ ((o >> 3) & 0x30); }
__device__ __forceinline__ float ex2(float x) {
    float y;
    asm("ex2.approx.ftz.f32 %0, %1;" : "=f"(y) : "f"(x));
    return y;
}

#define CP16(dst, src) asm volatile("cp.async.cg.shared.global [%0], [%1], 16;" :: "r"(dst), "l"(src))
#define CP_COMMIT()    asm volatile("cp.async.commit_group;" ::: "memory")
#define CP_WAIT1()     asm volatile("cp.async.wait_group 1;" ::: "memory")

__device__ __forceinline__ void mma_bf16(float* d, const uint32_t* a, const uint32_t* b) {
    asm volatile("mma.sync.aligned.m16n8k16.row.col.f32.bf16.bf16.f32 "
        "{%0,%1,%2,%3}, {%4,%5,%6,%7}, {%8,%9}, {%0,%1,%2,%3};"
        : "+f"(d[0]), "+f"(d[1]), "+f"(d[2]), "+f"(d[3])
        : "r"(a[0]), "r"(a[1]), "r"(a[2]), "r"(a[3]), "r"(b[0]), "r"(b[1]));
}
__device__ __forceinline__ void ldm_x4(uint32_t* r, uint32_t addr) {
    asm volatile("ldmatrix.sync.aligned.m8n8.x4.shared.b16 {%0,%1,%2,%3}, [%4];"
        : "=r"(r[0]), "=r"(r[1]), "=r"(r[2]), "=r"(r[3]) : "r"(addr));
}
__device__ __forceinline__ void ldm_x2(uint32_t* r, uint32_t addr) {
    asm volatile("ldmatrix.sync.aligned.m8n8.x2.shared.b16 {%0,%1}, [%2];"
        : "=r"(r[0]), "=r"(r[1]) : "r"(addr));
}
__device__ __forceinline__ void ldm_x4_t(uint32_t* r, uint32_t addr) {
    asm volatile("ldmatrix.sync.aligned.m8n8.x4.trans.shared.b16 {%0,%1,%2,%3}, [%4];"
        : "=r"(r[0]), "=r"(r[1]), "=r"(r[2]), "=r"(r[3]) : "r"(addr));
}
__device__ __forceinline__ uint32_t pack2(float a, float b) {
    __nv_bfloat162 hp = __floats2bfloat162_rn(a, b);
    return *(uint32_t*)&hp;
}

// ---------------- fused prep kernel ----------------
#define P_N0 (M_ * DIN_)
#define P_N1 (P_N0 + H_ * DIN_)
#define P_N2 (P_N1 + 3 * QKV_N * H_)
#define P_N3 (P_N2 + H_ * H_)
#define P_N4 (P_N3 + H_ * OCATN)
#define P_N5 (P_N4 + H_)
#define P_GRID ((P_N5 + 255) / 256)

__global__ void prep_kernel(const float* __restrict__ x, const float* __restrict__ W_in,
                            const float* __restrict__ ipw, const float* __restrict__ Wout,
                            const float* __restrict__ opw, const float* __restrict__ opb,
                            const float* __restrict__ sw)
{
    const int i = blockIdx.x * 256 + threadIdx.x;
    if (i < P_N0) {
        float v = x[i];
        bf16 h = __float2bfloat16(v);
        g_xh[i] = h;
        g_xl[i] = __float2bfloat16(v - __bfloat162float(h));
    } else if (i < P_N1) {
        const int j = i - P_N0;
        float v = W_in[j];
        bf16 h = __float2bfloat16(v);
        g_Winh[j] = h;
        g_Winl[j] = __float2bfloat16(v - __bfloat162float(h));
    } else if (i < P_N2) {
        const int j = i - P_N1;
        g_ipwh[j] = __float2bfloat16(ipw[j]);
    } else if (i < P_N3) {
        const int j = i - P_N2;
        g_Wouth[j] = __float2bfloat16(Wout[j]);
    } else if (i < P_N5) {
        float a = sw[0], b = sw[1], c = sw[2];
        float m = fmaxf(a, fmaxf(b, c));
        float e0 = expf(a - m), e1 = expf(b - m), e2 = expf(c - m);
        float inv = 1.0f / (e0 + e1 + e2);
        float w[3] = {e0 * inv, e1 * inv, e2 * inv};
        if (i < P_N4) {
            const int j = i - P_N3;
            const int h = j & 511;
            const int sc = (j >> 9) % 3;
            const int o = j / OCATN;
            g_opwh[j] = __float2bfloat16(w[sc] * opw[sc * (H_ * H_) + o * H_ + h]);
        } else {
            const int o = i - P_N4;
            g_bc[o] = w[0] * opb[o] + w[1] * opb[H_ + o] + w[2] * opb[2 * H_ + o];
        }
    }
}

// ---------------- HMMA GEMM, templated on split and M-tile ----------------
// BM=128: 8 warps (2m x 4n), warp tile 64x32. BM=64: warp tile 32x32.
// K-chunk 32, 3-stage, ONE barrier/chunk.
// modes: 0 = C fp32 + Chi, aux=pos (m%2048); 1 = qkv direct per-head writes;
//        2 = Chi only (+bias);               3 = C fp32, aux = residual
template<int SPLIT, int BM>
__global__ __launch_bounds__(256, 2)
void gemm_mma(const bf16* __restrict__ Ah, const bf16* __restrict__ Al,
              const bf16* __restrict__ Wh, const bf16* __restrict__ Wl,
              const float* __restrict__ bias, float* __restrict__ C,
              bf16* __restrict__ Chi,
              bf16* __restrict__ qh, bf16* __restrict__ kh, bf16* __restrict__ vh,
              int N, int K, int mode, const float* __restrict__ aux)
{
    constexpr int STAGE = SPLIT ? 32768 : 16384;
    constexpr int WOFF  = SPLIT ? 16384 : 8192;
    constexpr int MT    = BM / 32;        // mt iterations (4 or 2)
    extern __shared__ char sm[];
    const uint32_t sb = smem_u32(sm);
    const int tid = threadIdx.x, warp = tid >> 5, lane = tid & 31;
    const int warp_m = warp >> 2, warp_n = warp & 3;
    const int m0 = blockIdx.y * BM, n0 = blockIdx.x * 128;

    float acc[MT][4][4];
#pragma unroll
    for (int a = 0; a < MT; a++)
#pragma unroll
        for (int bq = 0; bq < 4; bq++)
#pragma unroll
            for (int c = 0; c < 4; c++) acc[a][bq][c] = 0.0f;

    const int NC = K >> 5;

    auto issue = [&](int c, int stg) {
        const int k0 = c << 5;
        const uint32_t st = sb + stg * STAGE;
        // A tile: BM rows x 4 float4 slots
#pragma unroll
        for (int e = tid; e < BM * 4; e += 256) {
            const int row = e >> 2, c16 = e & 3;
            const uint32_t so = swz64((uint32_t)(row * 64 + c16 * 16));
            CP16(st + so, Ah + (size_t)(m0 + row) * K + k0 + c16 * 8);
            if (SPLIT) CP16(st + 8192 + so, Al + (size_t)(m0 + row) * K + k0 + c16 * 8);
        }
        // W tile: 128 rows x 4 float4 slots
#pragma unroll
        for (int e = tid; e < 512; e += 256) {
            const int row = e >> 2, c16 = e & 3;
            const uint32_t so = swz64((uint32_t)(row * 64 + c16 * 16));
            CP16(st + WOFF + so, Wh + (size_t)(n0 + row) * K + k0 + c16 * 8);
            if (SPLIT) CP16(st + 24576 + so, Wl + (size_t)(n0 + row) * K + k0 + c16 * 8);
        }
    };

    issue(0, 0); CP_COMMIT();
    issue(1, 1); CP_COMMIT();

    int buf = 0;
    for (int c = 0; c < NC; c++) {
        CP_WAIT1();
        __syncthreads();
        if (c + 2 < NC) issue(c + 2, (buf + 2) % 3);
        CP_COMMIT();

        const uint32_t st = sb + buf * STAGE;
#pragma unroll
        for (int ks = 0; ks < 2; ks++) {
            uint32_t ah4[MT][4], al4[MT][4];
#pragma unroll
            for (int mt = 0; mt < MT; mt++) {
                uint32_t aoff = swz64((uint32_t)((warp_m * (BM / 2) + mt * 16 + (lane & 15)) * 64
                                    + ks * 32 + (lane >> 4) * 16));
                ldm_x4(ah4[mt], st + aoff);
                if (SPLIT) ldm_x4(al4[mt], st + 8192 + aoff);
            }
#pragma unroll
            for (int nt = 0; nt < 4; nt++) {
                uint32_t boff = swz64((uint32_t)((warp_n * 32 + nt * 8 + (lane & 7)) * 64
                                    + ks * 32 + ((lane >> 3) & 1) * 16));
                uint32_t bh2[2], bl2[2];
                ldm_x2(bh2, st + WOFF + boff);
                if (SPLIT) ldm_x2(bl2, st + 24576 + boff);
#pragma unroll
                for (int mt = 0; mt < MT; mt++) {
                    mma_bf16(acc[mt][nt], ah4[mt], bh2);
                    if (SPLIT) {
                        mma_bf16(acc[mt][nt], ah4[mt], bl2);
                        mma_bf16(acc[mt][nt], al4[mt], bh2);
                    }
                }
            }
        }
        buf = (buf + 1) % 3;
    }

    // ---- epilogue ----
#pragma unroll
    for (int mt = 0; mt < MT; mt++) {
#pragma unroll
        for (int nt = 0; nt < 4; nt++) {
            const int mrow = m0 + warp_m * (BM / 2) + mt * 16 + (lane >> 2);
            const int n = n0 + warp_n * 32 + nt * 8 + (lane & 3) * 2;
            const float2 b2 = *(const float2*)&bias[n];
#pragma unroll
            for (int half = 0; half < 2; half++) {
                const int m = mrow + half * 8;
                float2 v;
                v.x = acc[mt][nt][half * 2 + 0] + b2.x;
                v.y = acc[mt][nt][half * 2 + 1] + b2.y;
                if (mode == 0) {
                    float2 p = *(const float2*)&aux[(size_t)(m & (S_ - 1)) * N + n];
                    v.x += p.x; v.y += p.y;
                } else if (mode == 3) {
                    float2 p = *(const float2*)&aux[(size_t)m * N + n];
                    v.x += p.x; v.y += p.y;
                }
                if (mode == 1) {
                    const int i = n / QKV_N;
                    const int e = n - i * QKV_N;
                    const int t = e >> 9;
                    const int hd = (e >> 6) & 7;
                    const int dim = e & 63;
                    const int bb = m >> 11, ss = m & (S_ - 1);
                    const size_t dst = ((((size_t)i * BH_) + bb * NH_ + hd) * S_ + ss) * 64 + dim;
                    const float sc = (t == 0) ? (0.125f * LOG2E) : 1.0f;
                    bf16* ph = (t == 0) ? qh : (t == 1) ? kh : vh;
                    *(uint32_t*)&ph[dst] = pack2(v.x * sc, v.y * sc);
                } else {
                    if (C)   *(float2*)&C[(size_t)m * N + n] = v;
                    if (Chi) *(uint32_t*)&Chi[(size_t)m * N + n] = pack2(v.x, v.y);
                }
            }
        }
    }
}

// ---------------- HMMA flash attention (R15 proven, verbatim) ----------------
#define A_STG 16384
#define A_Q   (3 * A_STG)          // 49152
#define ASM_TOTAL (A_Q + 16384)    // 65536

__global__ __launch_bounds__(128, 2)
void attn_mma(const bf16* __restrict__ qh_, const bf16* __restrict__ kh_,
              const bf16* __restrict__ vh_, bf16* __restrict__ ohi)
{
    extern __shared__ char sm[];
    const uint32_t sb = smem_u32(sm);
    const int tid = threadIdx.x, warp = tid >> 5, lane = tid & 31;
    const int bh = blockIdx.y, b = bh >> 3, hd = bh & 7;
    const int z = blockIdx.z;
    const int scale = (z == 0) ? 5 : (z == 1) ? 21 : 63;
    const int q0 = blockIdx.x * 128;
    const int qw = warp * 32;

    const size_t zoff = ((size_t)z * BH_ + bh) * S_ * 64;
    const bf16* qh = qh_ + zoff;
    const bf16* kh = kh_ + zoff;
    const bf16* vh = vh_ + zoff;

    auto issue_kv = [&](int t, int stg) {
        const int kt = t * 64;
        const uint32_t st = sb + stg * A_STG;
#pragma unroll
        for (int e = tid; e < 512; e += 128) {
            const int row = e >> 3, c8 = e & 7;
            const uint32_t so = swz128((uint32_t)(row * 128 + c8 * 16));
            const size_t g = (size_t)(kt + row) * 64 + c8 * 8;
            CP16(st + so,        kh + g);
            CP16(st + 8192 + so, vh + g);
        }
    };

    for (int e = tid; e < 1024; e += 128) {
        const int row = e >> 3, c8 = e & 7;
        const uint32_t so = swz128((uint32_t)(row * 128 + c8 * 16));
        CP16(sb + A_Q + so, qh + (size_t)(q0 + row) * 64 + c8 * 8);
    }
    issue_kv(0, 0); CP_COMMIT();
    issue_kv(1, 1); CP_COMMIT();
    CP_WAIT1();
    __syncthreads();

    uint32_t qf[2][4][4];
#pragma unroll
    for (int h = 0; h < 2; h++)
#pragma unroll
        for (int ks = 0; ks < 4; ks++) {
            const uint32_t aoff = swz128((uint32_t)((qw + h * 16 + (lane & 15)) * 128
                                + (ks * 16 + (lane >> 4) * 8) * 2));
            ldm_x4(qf[h][ks], sb + A_Q + aoff);
        }

    const int rA = q0 + qw + (lane >> 2);
    const int rB = rA + 16;

    float o[2][8][4];
#pragma unroll
    for (int h = 0; h < 2; h++)
#pragma unroll
        for (int nt = 0; nt < 8; nt++)
#pragma unroll
            for (int c = 0; c < 4; c++) o[h][nt][c] = 0.0f;
    float lA0 = 0.f, lA1 = 0.f, lB0 = 0.f, lB1 = 0.f;

    const int NT = S_ / 64;
    int buf = 0;
    for (int t = 0; t < NT; t++) {
        const int kt = t * 64;
        CP_WAIT1();
        __syncthreads();
        if (t + 2 < NT) issue_kv(t + 2, (buf + 2) % 3);
        CP_COMMIT();

        const uint32_t st = sb + buf * A_STG;
        const bool tile_mask = (kt <= q0 + 127) && (kt + 63 >= q0 - scale);

#pragma unroll
        for (int c16 = 0; c16 < 4; c16++) {
            float s[2][2][4];
#pragma unroll
            for (int h = 0; h < 2; h++)
#pragma unroll
                for (int nb = 0; nb < 2; nb++)
#pragma unroll
                    for (int c = 0; c < 4; c++) s[h][nb][c] = 0.0f;

#pragma unroll
            for (int ks = 0; ks < 4; ks++) {
                const uint32_t boff = swz128((uint32_t)(
                    (c16 * 16 + (lane >> 4) * 8 + (lane & 7)) * 128
                    + (ks * 16 + ((lane >> 3) & 1) * 8) * 2));
                uint32_t kf[4];
                ldm_x4(kf, st + boff);
                mma_bf16(s[0][0], qf[0][ks], kf);
                mma_bf16(s[0][1], qf[0][ks], kf + 2);
                mma_bf16(s[1][0], qf[1][ks], kf);
                mma_bf16(s[1][1], qf[1][ks], kf + 2);
            }

            const int kc0 = kt + c16 * 16;
            if (tile_mask && kc0 <= q0 + 127 && kc0 + 15 >= q0 - scale) {
#pragma unroll
                for (int nb = 0; nb < 2; nb++) {
                    const int kj = kc0 + nb * 8 + (lane & 3) * 2;
#pragma unroll
                    for (int dk = 0; dk < 2; dk++) {
                        const int k = kj + dk;
                        if (k <= rA      && k >= rA - scale)      s[0][nb][dk]     = -1e30f;
                        if (k <= rA + 8  && k >= rA + 8 - scale)  s[0][nb][2 + dk] = -1e30f;
                        if (k <= rB      && k >= rB - scale)      s[1][nb][dk]     = -1e30f;
                        if (k <= rB + 8  && k >= rB + 8 - scale)  s[1][nb][2 + dk] = -1e30f;
                    }
                }
            }

            uint32_t pf[2][4];
#pragma unroll
            for (int h = 0; h < 2; h++) {
#pragma unroll
                for (int nb = 0; nb < 2; nb++)
#pragma unroll
                    for (int c = 0; c < 4; c++) s[h][nb][c] = ex2(s[h][nb][c]);
                pf[h][0] = pack2(s[h][0][0], s[h][0][1]);
                pf[h][1] = pack2(s[h][0][2], s[h][0][3]);
                pf[h][2] = pack2(s[h][1][0], s[h][1][1]);
                pf[h][3] = pack2(s[h][1][2], s[h][1][3]);
            }
            lA0 += s[0][0][0] + s[0][0][1] + s[0][1][0] + s[0][1][1];
            lA1 += s[0][0][2] + s[0][0][3] + s[0][1][2] + s[0][1][3];
            lB0 += s[1][0][0] + s[1][0][1] + s[1][1][0] + s[1][1][1];
            lB1 += s[1][0][2] + s[1][0][3] + s[1][1][2] + s[1][1][3];

#pragma unroll
            for (int dv = 0; dv < 4; dv++) {
                const uint32_t voff = swz128((uint32_t)(
                    (c16 * 16 + (lane & 15)) * 128
                    + (dv * 16 + (lane >> 4) * 8) * 2));
                uint32_t vf[4];
                ldm_x4_t(vf, st + 8192 + voff);
                mma_bf16(o[0][2 * dv],     pf[0], vf);
                mma_bf16(o[0][2 * dv + 1], pf[0], vf + 2);
                mma_bf16(o[1][2 * dv],     pf[1], vf);
                mma_bf16(o[1][2 * dv + 1], pf[1], vf + 2);
            }
        }
        buf = (buf + 1) % 3;
    }

    lA0 += __shfl_xor_sync(0xffffffffu, lA0, 1);
    lA0 += __shfl_xor_sync(0xffffffffu, lA0, 2);
    lA1 += __shfl_xor_sync(0xffffffffu, lA1, 1);
    lA1 += __shfl_xor_sync(0xffffffffu, lA1, 2);
    lB0 += __shfl_xor_sync(0xffffffffu, lB0, 1);
    lB0 += __shfl_xor_sync(0xffffffffu, lB0, 2);
    lB1 += __shfl_xor_sync(0xffffffffu, lB1, 1);
    lB1 += __shfl_xor_sync(0xffffffffu, lB1, 2);
    const float iA0 = 1.0f / lA0, iA1 = 1.0f / lA1;
    const float iB0 = 1.0f / lB0, iB1 = 1.0f / lB1;

#pragma unroll
    for (int h = 0; h < 2; h++) {
        const int row0 = (h == 0) ? rA : rB;
        const float i0 = (h == 0) ? iA0 : iB0;
        const float i1 = (h == 0) ? iA1 : iB1;
#pragma unroll
        for (int nt = 0; nt < 8; nt++) {
            const int col = nt * 8 + (lane & 3) * 2;
            const size_t base0 = (size_t)(b * S_ + row0)     * OCATN + z * H_ + hd * 64 + col;
            const size_t base1 = (size_t)(b * S_ + row0 + 8) * OCATN + z * H_ + hd * 64 + col;
            *(uint32_t*)&ohi[base0] = pack2(o[h][nt][0] * i0, o[h][nt][1] * i0);
            *(uint32_t*)&ohi[base1] = pack2(o[h][nt][2] * i1, o[h][nt][3] * i1);
        }
    }
}

// ---------------- layernorm ----------------
__global__ __launch_bounds__(256)
void ln_kernel(const float* __restrict__ res, const float* __restrict__ gamma,
               const float* __restrict__ beta, float* __restrict__ out)
{
    __shared__ float red[256];
    const int row = blockIdx.x;
    const int tid = threadIdx.x;
    const float* r = res + (size_t)row * H_;

    const float x0 = r[tid], x1 = r[tid + 256];
    red[tid] = x0 + x1;
    __syncthreads();
    for (int s = 128; s > 0; s >>= 1) {
        if (tid < s) red[tid] += red[tid + s];
        __syncthreads();
    }
    const float mu = red[0] * (1.0f / H_);
    __syncthreads();

    const float d0 = x0 - mu, d1 = x1 - mu;
    red[tid] = d0 * d0 + d1 * d1;
    __syncthreads();
    for (int s = 128; s > 0; s >>= 1) {
        if (tid < s) red[tid] += red[tid + s];
        __syncthreads();
    }
    const float var = red[0] * (1.0f / H_);
    const float inv = rsqrtf(var + 1e-5f);

    float* dst = out + (size_t)row * H_;
    dst[tid]       = d0 * inv * gamma[tid]       + beta[tid];
    dst[tid + 256] = d1 * inv * gamma[tid + 256] + beta[tid + 256];
}

// ---------------- launch ----------------
extern "C" void kernel_launch(void* const* d_in, const int* in_sizes, int n_in,
                              void* d_out, int out_size)
{
    const float* x          = (const float*)d_in[0];
    const float* pos        = (const float*)d_in[2];
    const float* W_in       = (const float*)d_in[3];
    const float* b_in       = (const float*)d_in[4];
    const float* in_proj_w  = (const float*)d_in[5];
    const float* in_proj_b  = (const float*)d_in[6];
    const float* out_proj_w = (const float*)d_in[7];
    const float* out_proj_b = (const float*)d_in[8];
    const float* sw         = (const float*)d_in[9];
    const float* W_out      = (const float*)d_in[10];
    const float* b_out      = (const float*)d_in[11];
    const float* ln_gamma   = (const float*)d_in[12];
    const float* ln_beta    = (const float*)d_in[13];
    float* out = (float*)d_out;

    float *h, *res, *bc;
    cudaGetSymbolAddress((void**)&h,   g_h);
    cudaGetSymbolAddress((void**)&res, g_res);
    cudaGetSymbolAddress((void**)&bc,  g_bc);
    bf16 *xh, *xl, *Winh, *Winl, *ipwh, *opwh, *Wouth;
    bf16 *hh, *qh, *kh, *vh, *oh, *cmh;
    cudaGetSymbolAddress((void**)&xh, g_xh);     cudaGetSymbolAddress((void**)&xl, g_xl);
    cudaGetSymbolAddress((void**)&Winh, g_Winh); cudaGetSymbolAddress((void**)&Winl, g_Winl);
    cudaGetSymbolAddress((void**)&ipwh, g_ipwh);
    cudaGetSymbolAddress((void**)&opwh, g_opwh);
    cudaGetSymbolAddress((void**)&Wouth, g_Wouth);
    cudaGetSymbolAddress((void**)&hh, g_hh);
    cudaGetSymbolAddress((void**)&qh, g_qh);
    cudaGetSymbolAddress((void**)&kh, g_kh);
    cudaGetSymbolAddress((void**)&vh, g_vh);
    cudaGetSymbolAddress((void**)&oh, g_oh);
    cudaGetSymbolAddress((void**)&cmh, g_cmh);

    cudaFuncSetAttribute((const void*)gemm_mma<1, 64>,  cudaFuncAttributeMaxDynamicSharedMemorySize, 98304);
    cudaFuncSetAttribute((const void*)gemm_mma<0, 128>, cudaFuncAttributeMaxDynamicSharedMemorySize, 49152);
    cudaFuncSetAttribute((const void*)gemm_mma<0, 64>,  cudaFuncAttributeMaxDynamicSharedMemorySize, 49152);
    cudaFuncSetAttribute((const void*)attn_mma,         cudaFuncAttributeMaxDynamicSharedMemorySize, ASM_TOTAL);

    // 0) all conversions + weight fusion in one kernel
    prep_kernel<<<P_GRID, 256>>>(x, W_in, in_proj_w, W_out, out_proj_w, out_proj_b, sw);

    // 1) h = x @ W_in^T + b_in + pos  (split; BM=64 -> grid 256)
    gemm_mma<1, 64><<<dim3(H_ / 128, M_ / 64), 256, 98304>>>(
        xh, xl, Winh, Winl, b_in, h, hh, 0, 0, 0, H_, DIN_, 0, pos);

    // 2) qkv for all 3 scales in one GEMM (N=4608), BM=128, direct per-head q/k/v
    gemm_mma<0, 128><<<dim3(NQKV / 128, M_ / 128), 256, 49152>>>(
        hh, (const bf16*)0, ipwh, (const bf16*)0, in_proj_b, (float*)0, (bf16*)0,
        qh, kh, vh, NQKV, H_, 1, (const float*)0);

    // 3) attention, all scales (grid.z), 32 q/warp, 64-key tiles, 3-stage
    attn_mma<<<dim3(S_ / 128, BH_, 3), 128, ASM_TOTAL>>>(qh, kh, vh, oh);

    // 4) comb = ocat @ Wc^T + bc (bf16 out; BM=64 -> grid 256)
    gemm_mma<0, 64><<<dim3(H_ / 128, M_ / 64), 256, 49152>>>(
        oh, (const bf16*)0, opwh, (const bf16*)0, bc, (float*)0, cmh,
        0, 0, 0, H_, OCATN, 2, (const float*)0);

    // 5) res = comb @ W_out^T + b_out + h (BM=64); then LN
    gemm_mma<0, 64><<<dim3(H_ / 128, M_ / 64), 256, 49152>>>(
        cmh, (const bf16*)0, Wouth, (const bf16*)0, b_out, res, (bf16*)0,
        0, 0, 0, H_, H_, 3, h);
    ln_kernel<<<M_, 256>>>(res, ln_gamma, ln_beta, out);
}